// round 6
// baseline (speedup 1.0000x reference)
#include <cuda_runtime.h>

#define BB 16
#define QQ 300
#define SNUM 16
#define HID 256
#define T_TOT 13125
#define W0 100
#define H0 100
#define QP 3
#define S_SCALE_C 0.077f
#define NBLK 192
#define RB 4                        // rows per block (192*4 = 768)
#define NTHR 512
#define CH 128                      // c-half length
#define ITEMS (BB * QQ * SNUM)      // 76800
#define PER_BLK (ITEMS / NBLK)      // 400

__device__ __align__(16) float g_off[BB * QP * SNUM * 4];
__device__ unsigned g_cnt;          // cumulative across launches, never reset

typedef unsigned long long ull;

__device__ __forceinline__ ull pack2(float lo, float hi) {
    ull r; asm("mov.b64 %0, {%1, %2};" : "=l"(r) : "f"(lo), "f"(hi)); return r;
}
__device__ __forceinline__ void unpack2(ull v, float& lo, float& hi) {
    asm("mov.b64 {%0, %1}, %2;" : "=f"(lo), "=f"(hi) : "l"(v));
}
__device__ __forceinline__ void fma2(ull& d, ull a, ull b) {
    asm("fma.rn.f32x2 %0, %1, %2, %3;" : "=l"(d) : "l"(a), "l"(b), "l"(d));
}
__device__ __forceinline__ float tanh_fast(float x) {
    float r; asm("tanh.approx.f32 %0, %1;" : "=f"(r) : "f"(x)); return r;
}
__device__ __forceinline__ unsigned ld_cg_u32(const unsigned* p) {
    unsigned v; asm volatile("ld.global.cg.u32 %0, [%1];" : "=r"(v) : "l"(p)); return v;
}

__device__ __forceinline__ void poly_xy(const float* __restrict__ c, int s,
                                        float& spx, float& spy) {
    const float t  = (float)s * (1.0f / (float)(SNUM - 1));
    const float t2 = t * t, t3 = t2 * t;
    spx = 2.0f * (c[0] * t3 + c[1] * t2 + c[2] * t + c[3] - 0.5f);
    spy = 2.0f * (c[4] * t3 + c[5] * t2 + c[6] * t + c[7] - 0.5f);
}

__global__ __launch_bounds__(NTHR, 2) void fused_kernel(
        const float* __restrict__ rp,
        const float* __restrict__ mem,
        const float* __restrict__ w1,
        const float* __restrict__ b1,
        const float* __restrict__ w2,
        const float* __restrict__ b2,
        const int* __restrict__ rl,
        float* __restrict__ out) {
    const int blk = blockIdx.x;
    const int tid = threadIdx.x;

    // pool: gather staging [4][256] (4KB) first, later partial sums [2][256][4] (8KB)
    __shared__ __align__(16) float pool[2 * HID * RB];     // 8KB
    __shared__ __align__(16) float gsp[HID * RB];          // 4KB  [c][r] packed
    __shared__ __align__(16) float h1s[RB * HID];          // 4KB  [r][o]
    __shared__ unsigned sh_tgt;

    // ============ gather: 128 threads/row, 2 channels each (float2) ============
    {
        const int r = tid >> 7;            // 0..3
        const int u = tid & 127;           // channel pair
        const int row = blk * RB + r;      // b*48 + qp*16 + s
        const int s  = row & 15;
        const int qp = (row >> 4) % QP;
        const int b  = row / (QP * SNUM);

        float gx, gy;
        poly_xy(rp + ((size_t)b * QQ + qp) * 8, s, gx, gy);
        const float x = (gx + 1.0f) * (W0 * 0.5f) - 0.5f;
        const float y = (gy + 1.0f) * (H0 * 0.5f) - 0.5f;
        const float x0f = floorf(x), y0f = floorf(y);
        const int x0 = (int)x0f, y0 = (int)y0f;
        const float wx1 = x - x0f, wx0 = 1.0f - wx1;
        const float wy1 = y - y0f, wy0 = 1.0f - wy1;

        const float* memb = mem + (size_t)b * T_TOT * HID;
        float2 a = make_float2(0.f, 0.f);
        #pragma unroll
        for (int dy = 0; dy < 2; dy++) {
            const int yi = y0 + dy;
            if (yi < 0 || yi >= H0) continue;
            const float wy = dy ? wy1 : wy0;
            #pragma unroll
            for (int dx = 0; dx < 2; dx++) {
                const int xi = x0 + dx;
                if (xi < 0 || xi >= W0) continue;
                const float wgt = wy * (dx ? wx1 : wx0);
                const float2 v = __ldg(reinterpret_cast<const float2*>(
                    memb + (size_t)(yi * W0 + xi) * HID + u * 2));
                a.x += wgt * v.x;
                a.y += wgt * v.y;
            }
        }
        *reinterpret_cast<float2*>(&pool[r * HID + u * 2]) = a;
    }
    __syncthreads();

    // ============ transpose [r][c] -> packed [c][r] ============
    if (tid < HID) {
        float4 p;
        p.x = pool[0 * HID + tid]; p.y = pool[1 * HID + tid];
        p.z = pool[2 * HID + tid]; p.w = pool[3 * HID + tid];
        *reinterpret_cast<float4*>(&gsp[tid * RB]) = p;
    }
    __syncthreads();

    // ============ layer 1: thread = (output o, c-half), 128-iter loop ============
    {
        const int o  = tid & (HID - 1);
        const int ch = tid >> 8;           // 0 or 1
        const int cb = ch * CH;

        ull a0 = 0, a1 = 0;                // 4 rows packed
        const float* wcol = w1 + (size_t)cb * HID + o;
        const float* gp   = &gsp[cb * RB];
        #pragma unroll 8
        for (int c = 0; c < CH; c++) {
            const float w = __ldg(wcol + c * HID);
            const ull wp = pack2(w, w);
            const ull g0 = *reinterpret_cast<const ull*>(gp + c * RB + 0);
            const ull g1 = *reinterpret_cast<const ull*>(gp + c * RB + 2);
            fma2(a0, g0, wp);
            fma2(a1, g1, wp);
        }
        // store partials: pool[ch][o][0..3]
        float* dst = &pool[(ch * HID + o) * RB];
        float v0, v1;
        unpack2(a0, v0, v1);
        dst[0] = v0; dst[1] = v1;
        unpack2(a1, v0, v1);
        dst[2] = v0; dst[3] = v1;
    }
    __syncthreads();

    // ============ combine halves + bias + tanh -> h1s[r][o] ============
    if (tid < HID) {
        const float bv = __ldg(&b1[tid]);
        const float4 p0 = *reinterpret_cast<const float4*>(&pool[tid * RB]);
        const float4 p1 = *reinterpret_cast<const float4*>(&pool[(HID + tid) * RB]);
        h1s[0 * HID + tid] = tanh_fast(p0.x + p1.x + bv);
        h1s[1 * HID + tid] = tanh_fast(p0.y + p1.y + bv);
        h1s[2 * HID + tid] = tanh_fast(p0.z + p1.z + bv);
        h1s[3 * HID + tid] = tanh_fast(p0.w + p1.w + bv);
    }
    __syncthreads();

    // ============ layer 2: warp w (<4) = row w, 4 outputs via float4 w2 ============
    if (tid < 128) {
        const int wid = tid >> 5, lane = tid & 31;
        float a0 = 0.f, a1 = 0.f, a2 = 0.f, a3 = 0.f;
        const float4* w2v = reinterpret_cast<const float4*>(w2);
        #pragma unroll
        for (int j = lane; j < HID; j += 32) {
            const float h = h1s[wid * HID + j];
            const float4 wr = __ldg(&w2v[j]);
            a0 += h * wr.x; a1 += h * wr.y; a2 += h * wr.z; a3 += h * wr.w;
        }
        #pragma unroll
        for (int o = 16; o > 0; o >>= 1) {
            a0 += __shfl_xor_sync(0xffffffffu, a0, o);
            a1 += __shfl_xor_sync(0xffffffffu, a1, o);
            a2 += __shfl_xor_sync(0xffffffffu, a2, o);
            a3 += __shfl_xor_sync(0xffffffffu, a3, o);
        }
        if (lane == 0) {
            const float4 bb = __ldg(reinterpret_cast<const float4*>(b2));
            float4 ov;
            ov.x = S_SCALE_C * tanh_fast(a0 + bb.x);
            ov.y = S_SCALE_C * tanh_fast(a1 + bb.y);
            ov.z = S_SCALE_C * tanh_fast(a2 + bb.z);
            ov.w = S_SCALE_C * tanh_fast(a3 + bb.w);
            reinterpret_cast<float4*>(g_off)[blk * RB + wid] = ov;
        }
    }
    __threadfence();
    __syncthreads();

    // arrive
    if (tid == 0) {
        const unsigned t = atomicAdd(&g_cnt, 1u);
        sh_tgt = t - (t % NBLK) + NBLK;
    }

    // ============ phase B prologue (independent of g_off) ============
    float spx = 0.f, spy = 0.f;
    int lvl = 0, bI = 0, sI = 0;
    const int idx = blk * PER_BLK + tid;
    const bool valid = (tid < PER_BLK);
    if (valid) {
        const int s  = idx & 15;
        const int qb = idx >> 4;
        const int q  = qb % QQ;
        const int b  = qb / QQ;
        poly_xy(rp + ((size_t)b * QQ + q) * 8, s, spx, spy);
        lvl = rl[b * QQ + q];
        bI = b; sI = s;
    }

    // ============ global barrier ============
    __syncthreads();
    if (tid == 0) {
        const unsigned tgt = sh_tgt;
        while ((int)(ld_cg_u32(&g_cnt) - tgt) < 0)
            __nanosleep(32);
    }
    __syncthreads();
    __threadfence();                         // acquire

    // ============ epilogue ============
    if (valid) {
        const float* o = g_off + (((size_t)bI * QP + lvl) * SNUM + sI) * 4;
        const float4 ov = __ldcg(reinterpret_cast<const float4*>(o));
        float4 v;
        v.x = ov.x + spx;
        v.y = ov.y + spy;
        v.z = ov.z + spx;
        v.w = ov.w + spy;
        reinterpret_cast<float4*>(out)[idx] = v;
    }
}

extern "C" void kernel_launch(void* const* d_in, const int* in_sizes, int n_in,
                              void* d_out, int out_size) {
    const float* ref_polys = (const float*)d_in[0];
    const float* memory    = (const float*)d_in[1];
    const float* w1        = (const float*)d_in[2];
    const float* b1        = (const float*)d_in[3];
    const float* w2        = (const float*)d_in[4];
    const float* b2        = (const float*)d_in[5];
    const int*   ref_lvls  = (const int*)d_in[6];
    float* out = (float*)d_out;

    fused_kernel<<<NBLK, NTHR>>>(ref_polys, memory, w1, b1, w2, b2, ref_lvls, out);
}

// round 7
// speedup vs baseline: 1.2162x; 1.2162x over previous
#include <cuda_runtime.h>
#include <cstdint>

#define BB 16
#define QQ 300
#define SNUM 16
#define HID 256
#define T_TOT 13125
#define W0 100
#define H0 100
#define QP 3
#define S_SCALE_C 0.077f
#define NBLK 192
#define RB 4                        // rows per block (192*4 = 768)
#define NTHR 512
#define TC 32                       // w1 tile: input channels per tile
#define NTILE (HID / TC)            // 8
#define ITEMS (BB * QQ * SNUM)      // 76800
#define PER_BLK (ITEMS / NBLK)      // 400

// dynamic smem layout (bytes)
#define W1S_OFF   0                          // 2 x 32KB tile buffers
#define W1S_BYTES (TC * HID * 4)             // 32768
#define POOL_OFF  (2 * W1S_BYTES)            // 8KB: gather staging then partials
#define GSP_OFF   (POOL_OFF + 2 * HID * RB * 4)   // 4KB [c][r]
#define H1S_OFF   (GSP_OFF + HID * RB * 4)        // 4KB [r][o]
#define SMEM_BYTES (H1S_OFF + RB * HID * 4)       // 81920

__device__ __align__(16) float g_off[BB * QP * SNUM * 4];
__device__ unsigned g_cnt;          // cumulative across launches, never reset

typedef unsigned long long ull;

__device__ __forceinline__ ull pack2(float lo, float hi) {
    ull r; asm("mov.b64 %0, {%1, %2};" : "=l"(r) : "f"(lo), "f"(hi)); return r;
}
__device__ __forceinline__ void unpack2(ull v, float& lo, float& hi) {
    asm("mov.b64 {%0, %1}, %2;" : "=f"(lo), "=f"(hi) : "l"(v));
}
__device__ __forceinline__ void fma2(ull& d, ull a, ull b) {
    asm("fma.rn.f32x2 %0, %1, %2, %3;" : "=l"(d) : "l"(a), "l"(b), "l"(d));
}
__device__ __forceinline__ float tanh_fast(float x) {
    float r; asm("tanh.approx.f32 %0, %1;" : "=f"(r) : "f"(x)); return r;
}
__device__ __forceinline__ unsigned ld_cg_u32(const unsigned* p) {
    unsigned v; asm volatile("ld.global.cg.u32 %0, [%1];" : "=r"(v) : "l"(p)); return v;
}
__device__ __forceinline__ void cp16(uint32_t dst, const void* src) {
    asm volatile("cp.async.ca.shared.global [%0], [%1], 16;" :: "r"(dst), "l"(src));
}

__device__ __forceinline__ void poly_xy(const float* __restrict__ c, int s,
                                        float& spx, float& spy) {
    const float t  = (float)s * (1.0f / (float)(SNUM - 1));
    const float t2 = t * t, t3 = t2 * t;
    spx = 2.0f * (c[0] * t3 + c[1] * t2 + c[2] * t + c[3] - 0.5f);
    spy = 2.0f * (c[4] * t3 + c[5] * t2 + c[6] * t + c[7] - 0.5f);
}

__global__ __launch_bounds__(NTHR, 2) void fused_kernel(
        const float* __restrict__ rp,
        const float* __restrict__ mem,
        const float* __restrict__ w1,
        const float* __restrict__ b1,
        const float* __restrict__ w2,
        const float* __restrict__ b2,
        const int* __restrict__ rl,
        float* __restrict__ out) {
    extern __shared__ __align__(16) char smem[];
    float* pool = reinterpret_cast<float*>(smem + POOL_OFF);
    float* gsp  = reinterpret_cast<float*>(smem + GSP_OFF);
    float* h1s  = reinterpret_cast<float*>(smem + H1S_OFF);
    __shared__ unsigned sh_tgt;

    const int blk = blockIdx.x;
    const int tid = threadIdx.x;
    const uint32_t smem_b = (uint32_t)__cvta_generic_to_shared(smem);

    // ---- kick off w1 tile prefetch for tiles 0 and 1 (overlaps the gather) ----
    {
        #pragma unroll
        for (int t = 0; t < 2; t++) {
            const float4* src = reinterpret_cast<const float4*>(w1 + t * TC * HID);
            const uint32_t dst = smem_b + W1S_OFF + t * W1S_BYTES + tid * 16;
            #pragma unroll
            for (int k = 0; k < 4; k++)
                cp16(dst + k * (NTHR * 16), src + tid + k * NTHR);
            asm volatile("cp.async.commit_group;");
        }
    }

    // ============ gather: 128 threads/row, 2 channels each (float2) ============
    {
        const int r = tid >> 7;            // 0..3
        const int u = tid & 127;           // channel pair
        const int row = blk * RB + r;      // b*48 + qp*16 + s
        const int s  = row & 15;
        const int qp = (row >> 4) % QP;
        const int b  = row / (QP * SNUM);

        float gx, gy;
        poly_xy(rp + ((size_t)b * QQ + qp) * 8, s, gx, gy);
        const float x = (gx + 1.0f) * (W0 * 0.5f) - 0.5f;
        const float y = (gy + 1.0f) * (H0 * 0.5f) - 0.5f;
        const float x0f = floorf(x), y0f = floorf(y);
        const int x0 = (int)x0f, y0 = (int)y0f;
        const float wx1 = x - x0f, wx0 = 1.0f - wx1;
        const float wy1 = y - y0f, wy0 = 1.0f - wy1;

        const float* memb = mem + (size_t)b * T_TOT * HID;
        float2 a = make_float2(0.f, 0.f);
        #pragma unroll
        for (int dy = 0; dy < 2; dy++) {
            const int yi = y0 + dy;
            if (yi < 0 || yi >= H0) continue;
            const float wy = dy ? wy1 : wy0;
            #pragma unroll
            for (int dx = 0; dx < 2; dx++) {
                const int xi = x0 + dx;
                if (xi < 0 || xi >= W0) continue;
                const float wgt = wy * (dx ? wx1 : wx0);
                const float2 v = __ldg(reinterpret_cast<const float2*>(
                    memb + (size_t)(yi * W0 + xi) * HID + u * 2));
                a.x += wgt * v.x;
                a.y += wgt * v.y;
            }
        }
        *reinterpret_cast<float2*>(&pool[r * HID + u * 2]) = a;
    }
    __syncthreads();

    // ============ transpose [r][c] -> packed [c][r] ============
    if (tid < HID) {
        float4 p;
        p.x = pool[0 * HID + tid]; p.y = pool[1 * HID + tid];
        p.z = pool[2 * HID + tid]; p.w = pool[3 * HID + tid];
        *reinterpret_cast<float4*>(&gsp[tid * RB]) = p;
    }
    __syncthreads();

    // ============ layer 1: cp.async double-buffered w1 tiles ============
    // thread = (o = tid&255, ch = tid>>8); ch 0 -> first 16 c of each tile,
    // ch 1 -> last 16. Partial sums combined after.
    {
        const int o  = tid & (HID - 1);
        const int ch = tid >> 8;           // 0 or 1
        ull a0 = 0, a1 = 0;                // 4 rows packed

        #pragma unroll 1
        for (int t = 0; t < NTILE; t++) {
            if (t < NTILE - 1) { asm volatile("cp.async.wait_group 1;"); }
            else               { asm volatile("cp.async.wait_group 0;"); }
            __syncthreads();

            const float* wt = reinterpret_cast<const float*>(
                smem + W1S_OFF + (t & 1) * W1S_BYTES);
            const int cg0 = t * TC + ch * (TC / 2);
            const float* wp_base = wt + (ch * (TC / 2)) * HID + o;
            #pragma unroll
            for (int cc = 0; cc < TC / 2; cc++) {
                const float w = wp_base[cc * HID];
                const ull wv = pack2(w, w);
                const float* g = &gsp[(cg0 + cc) * RB];
                const ull g0 = *reinterpret_cast<const ull*>(g + 0);
                const ull g1 = *reinterpret_cast<const ull*>(g + 2);
                fma2(a0, g0, wv);
                fma2(a1, g1, wv);
            }
            __syncthreads();
            if (t + 2 < NTILE) {
                const float4* src = reinterpret_cast<const float4*>(
                    w1 + (t + 2) * TC * HID);
                const uint32_t dst = smem_b + W1S_OFF + (t & 1) * W1S_BYTES + tid * 16;
                #pragma unroll
                for (int k = 0; k < 4; k++)
                    cp16(dst + k * (NTHR * 16), src + tid + k * NTHR);
                asm volatile("cp.async.commit_group;");
            }
        }

        // store partials: pool[ch][o][0..3]
        float* dst = &pool[(ch * HID + o) * RB];
        float v0, v1;
        unpack2(a0, v0, v1);
        dst[0] = v0; dst[1] = v1;
        unpack2(a1, v0, v1);
        dst[2] = v0; dst[3] = v1;
    }
    __syncthreads();

    // ============ combine halves + bias + tanh -> h1s[r][o] ============
    if (tid < HID) {
        const float bv = __ldg(&b1[tid]);
        const float4 p0 = *reinterpret_cast<const float4*>(&pool[tid * RB]);
        const float4 p1 = *reinterpret_cast<const float4*>(&pool[(HID + tid) * RB]);
        h1s[0 * HID + tid] = tanh_fast(p0.x + p1.x + bv);
        h1s[1 * HID + tid] = tanh_fast(p0.y + p1.y + bv);
        h1s[2 * HID + tid] = tanh_fast(p0.z + p1.z + bv);
        h1s[3 * HID + tid] = tanh_fast(p0.w + p1.w + bv);
    }
    __syncthreads();

    // ============ layer 2: warp w (<4) = row w, 4 outputs via float4 w2 ============
    if (tid < 128) {
        const int wid = tid >> 5, lane = tid & 31;
        float a0 = 0.f, a1 = 0.f, a2 = 0.f, a3 = 0.f;
        const float4* w2v = reinterpret_cast<const float4*>(w2);
        #pragma unroll
        for (int j = lane; j < HID; j += 32) {
            const float h = h1s[wid * HID + j];
            const float4 wr = __ldg(&w2v[j]);
            a0 += h * wr.x; a1 += h * wr.y; a2 += h * wr.z; a3 += h * wr.w;
        }
        #pragma unroll
        for (int o = 16; o > 0; o >>= 1) {
            a0 += __shfl_xor_sync(0xffffffffu, a0, o);
            a1 += __shfl_xor_sync(0xffffffffu, a1, o);
            a2 += __shfl_xor_sync(0xffffffffu, a2, o);
            a3 += __shfl_xor_sync(0xffffffffu, a3, o);
        }
        if (lane == 0) {
            const float4 bb = __ldg(reinterpret_cast<const float4*>(b2));
            float4 ov;
            ov.x = S_SCALE_C * tanh_fast(a0 + bb.x);
            ov.y = S_SCALE_C * tanh_fast(a1 + bb.y);
            ov.z = S_SCALE_C * tanh_fast(a2 + bb.z);
            ov.w = S_SCALE_C * tanh_fast(a3 + bb.w);
            reinterpret_cast<float4*>(g_off)[blk * RB + wid] = ov;
        }
    }
    __threadfence();
    __syncthreads();

    // arrive
    if (tid == 0) {
        const unsigned t = atomicAdd(&g_cnt, 1u);
        sh_tgt = t - (t % NBLK) + NBLK;
    }

    // ============ phase B prologue (independent of g_off) ============
    float spx = 0.f, spy = 0.f;
    int lvl = 0, bI = 0, sI = 0;
    const int idx = blk * PER_BLK + tid;
    const bool valid = (tid < PER_BLK);
    if (valid) {
        const int s  = idx & 15;
        const int qb = idx >> 4;
        const int q  = qb % QQ;
        const int b  = qb / QQ;
        poly_xy(rp + ((size_t)b * QQ + q) * 8, s, spx, spy);
        lvl = rl[b * QQ + q];
        bI = b; sI = s;
    }

    // ============ global barrier ============
    __syncthreads();
    if (tid == 0) {
        const unsigned tgt = sh_tgt;
        while ((int)(ld_cg_u32(&g_cnt) - tgt) < 0)
            __nanosleep(32);
    }
    __syncthreads();
    __threadfence();                         // acquire

    // ============ epilogue ============
    if (valid) {
        const float* o = g_off + (((size_t)bI * QP + lvl) * SNUM + sI) * 4;
        const float4 ov = __ldcg(reinterpret_cast<const float4*>(o));
        float4 v;
        v.x = ov.x + spx;
        v.y = ov.y + spy;
        v.z = ov.z + spx;
        v.w = ov.w + spy;
        reinterpret_cast<float4*>(out)[idx] = v;
    }
}

extern "C" void kernel_launch(void* const* d_in, const int* in_sizes, int n_in,
                              void* d_out, int out_size) {
    const float* ref_polys = (const float*)d_in[0];
    const float* memory    = (const float*)d_in[1];
    const float* w1        = (const float*)d_in[2];
    const float* b1        = (const float*)d_in[3];
    const float* w2        = (const float*)d_in[4];
    const float* b2        = (const float*)d_in[5];
    const int*   ref_lvls  = (const int*)d_in[6];
    float* out = (float*)d_out;

    cudaFuncSetAttribute(fused_kernel,
                         cudaFuncAttributeMaxDynamicSharedMemorySize, SMEM_BYTES);
    fused_kernel<<<NBLK, NTHR, SMEM_BYTES>>>(ref_polys, memory, w1, b1, w2, b2,
                                             ref_lvls, out);
}

// round 8
// speedup vs baseline: 1.3433x; 1.1045x over previous
#include <cuda_runtime.h>
#include <cstdint>

#define BB 16
#define QQ 300
#define SNUM 16
#define HID 256
#define T_TOT 13125
#define W0 100
#define H0 100
#define QP 3
#define S_SCALE_C 0.077f
#define NBLK 128
#define RB 6                        // rows per block (128*6 = 768)
#define NTHR 512
#define TC 32                       // w1 tile: input channels per tile
#define NTILE (HID / TC)            // 8
#define ITEMS (BB * QQ * SNUM)      // 76800
#define PER_BLK (ITEMS / NBLK)      // 600

// dynamic smem layout (bytes)
#define W1S_BYTES (TC * HID * 4)                   // 32768 per buffer
#define POOL_OFF  (2 * W1S_BYTES)                  // partials [2][256][6] = 12KB
#define GSP_OFF   (POOL_OFF + 2 * HID * RB * 4)    // packed [c][r] 6KB
#define H1S_OFF   (GSP_OFF + HID * RB * 4)         // [r][o] 6KB
#define SMEM_BYTES (H1S_OFF + RB * HID * 4)        // 90112

__device__ __align__(16) float g_off[BB * QP * SNUM * 4];
__device__ unsigned g_cnt;          // cumulative across launches, never reset

typedef unsigned long long ull;

__device__ __forceinline__ ull pack2(float lo, float hi) {
    ull r; asm("mov.b64 %0, {%1, %2};" : "=l"(r) : "f"(lo), "f"(hi)); return r;
}
__device__ __forceinline__ void unpack2(ull v, float& lo, float& hi) {
    asm("mov.b64 {%0, %1}, %2;" : "=f"(lo), "=f"(hi) : "l"(v));
}
__device__ __forceinline__ void fma2(ull& d, ull a, ull b) {
    asm("fma.rn.f32x2 %0, %1, %2, %3;" : "=l"(d) : "l"(a), "l"(b), "l"(d));
}
__device__ __forceinline__ float tanh_fast(float x) {
    float r; asm("tanh.approx.f32 %0, %1;" : "=f"(r) : "f"(x)); return r;
}
__device__ __forceinline__ unsigned ld_cg_u32(const unsigned* p) {
    unsigned v; asm volatile("ld.global.cg.u32 %0, [%1];" : "=r"(v) : "l"(p)); return v;
}
__device__ __forceinline__ void cp16(uint32_t dst, const void* src) {
    asm volatile("cp.async.ca.shared.global [%0], [%1], 16;" :: "r"(dst), "l"(src));
}

__device__ __forceinline__ void poly_xy(const float* __restrict__ c, int s,
                                        float& spx, float& spy) {
    const float t  = (float)s * (1.0f / (float)(SNUM - 1));
    const float t2 = t * t, t3 = t2 * t;
    spx = 2.0f * (c[0] * t3 + c[1] * t2 + c[2] * t + c[3] - 0.5f);
    spy = 2.0f * (c[4] * t3 + c[5] * t2 + c[6] * t + c[7] - 0.5f);
}

__global__ __launch_bounds__(NTHR, 1) void fused_kernel(
        const float* __restrict__ rp,
        const float* __restrict__ mem,
        const float* __restrict__ w1,
        const float* __restrict__ b1,
        const float* __restrict__ w2,
        const float* __restrict__ b2,
        const int* __restrict__ rl,
        float* __restrict__ out) {
    extern __shared__ __align__(16) char smem[];
    float* pool = reinterpret_cast<float*>(smem + POOL_OFF);   // partials [2][256][6]
    float* gsp  = reinterpret_cast<float*>(smem + GSP_OFF);    // [c][r]
    float* h1s  = reinterpret_cast<float*>(smem + H1S_OFF);    // [r][o]
    __shared__ unsigned sh_tgt;

    const int blk = blockIdx.x;
    const int tid = threadIdx.x;
    const uint32_t smem_b = (uint32_t)__cvta_generic_to_shared(smem);

    // ---- kick off w1 tile prefetch for tiles 0 and 1 (overlaps the gather) ----
    #pragma unroll
    for (int t = 0; t < 2; t++) {
        const float4* src = reinterpret_cast<const float4*>(w1 + t * TC * HID);
        const uint32_t dst = smem_b + t * W1S_BYTES + tid * 16;
        #pragma unroll
        for (int k = 0; k < 4; k++)
            cp16(dst + k * (NTHR * 16), src + tid + k * NTHR);
        asm volatile("cp.async.commit_group;");
    }

    // ============ gather: flat loop, 3 iters/thread, packed write [c][r] ============
    {
        #pragma unroll
        for (int it = 0; it < RB * HID / NTHR; it++) {
            const int e = it * NTHR + tid;       // 0..1535
            const int r = e >> 8;                // row 0..5
            const int c = e & 255;               // channel
            const int row = blk * RB + r;
            const int s  = row & 15;
            const int qp = (row >> 4) % QP;
            const int b  = row / (QP * SNUM);

            float gx, gy;
            poly_xy(rp + ((size_t)b * QQ + qp) * 8, s, gx, gy);
            const float x = (gx + 1.0f) * (W0 * 0.5f) - 0.5f;
            const float y = (gy + 1.0f) * (H0 * 0.5f) - 0.5f;
            const float x0f = floorf(x), y0f = floorf(y);
            const int x0 = (int)x0f, y0 = (int)y0f;
            const float wx1 = x - x0f, wx0 = 1.0f - wx1;
            const float wy1 = y - y0f, wy0 = 1.0f - wy1;

            const float* memb = mem + (size_t)b * T_TOT * HID + c;
            float a = 0.0f;
            #pragma unroll
            for (int dy = 0; dy < 2; dy++) {
                const int yi = y0 + dy;
                if (yi < 0 || yi >= H0) continue;
                const float wy = dy ? wy1 : wy0;
                #pragma unroll
                for (int dx = 0; dx < 2; dx++) {
                    const int xi = x0 + dx;
                    if (xi < 0 || xi >= W0) continue;
                    a += wy * (dx ? wx1 : wx0) *
                         __ldg(memb + (size_t)(yi * W0 + xi) * HID);
                }
            }
            gsp[c * RB + r] = a;
        }
    }
    __syncthreads();

    // ============ layer 1: cp.async double-buffered w1, 2-way c-split ============
    {
        const int o  = tid & (HID - 1);
        const int ch = tid >> 8;               // 0 or 1 (c-half within each tile)
        ull a0 = 0, a1 = 0, a2 = 0;            // 6 rows packed pairwise

        #pragma unroll 1
        for (int t = 0; t < NTILE; t++) {
            if (t < NTILE - 1) { asm volatile("cp.async.wait_group 1;"); }
            else               { asm volatile("cp.async.wait_group 0;"); }
            __syncthreads();

            const float* wt = reinterpret_cast<const float*>(
                smem + (t & 1) * W1S_BYTES) + (ch * (TC / 2)) * HID + o;
            const float* gb = &gsp[(t * TC + ch * (TC / 2)) * RB];
            #pragma unroll
            for (int cc = 0; cc < TC / 2; cc++) {
                const float w = wt[cc * HID];
                const ull wv = pack2(w, w);
                const float* g = gb + cc * RB;
                fma2(a0, *reinterpret_cast<const ull*>(g + 0), wv);
                fma2(a1, *reinterpret_cast<const ull*>(g + 2), wv);
                fma2(a2, *reinterpret_cast<const ull*>(g + 4), wv);
            }
            __syncthreads();
            if (t + 2 < NTILE) {
                const float4* src = reinterpret_cast<const float4*>(
                    w1 + (t + 2) * TC * HID);
                const uint32_t dst = smem_b + (t & 1) * W1S_BYTES + tid * 16;
                #pragma unroll
                for (int k = 0; k < 4; k++)
                    cp16(dst + k * (NTHR * 16), src + tid + k * NTHR);
                asm volatile("cp.async.commit_group;");
            }
        }

        // store partials: pool[(ch*256 + o)*6 + r]
        float* dst = &pool[(ch * HID + o) * RB];
        float v0, v1;
        unpack2(a0, v0, v1); dst[0] = v0; dst[1] = v1;
        unpack2(a1, v0, v1); dst[2] = v0; dst[3] = v1;
        unpack2(a2, v0, v1); dst[4] = v0; dst[5] = v1;
    }
    __syncthreads();

    // ============ combine halves + bias + tanh -> h1s[r][o] ============
    if (tid < HID) {
        const float bv = __ldg(&b1[tid]);
        const float* p0 = &pool[tid * RB];
        const float* p1 = &pool[(HID + tid) * RB];
        #pragma unroll
        for (int r = 0; r < RB; r++)
            h1s[r * HID + tid] = tanh_fast(p0[r] + p1[r] + bv);
    }
    __syncthreads();

    // ============ layer 2: warp w (<6) = row w, 4 outputs via float4 w2 ============
    if (tid < RB * 32) {
        const int wid = tid >> 5, lane = tid & 31;
        float a0 = 0.f, a1 = 0.f, a2 = 0.f, a3 = 0.f;
        const float4* w2v = reinterpret_cast<const float4*>(w2);
        #pragma unroll
        for (int j = lane; j < HID; j += 32) {
            const float h = h1s[wid * HID + j];
            const float4 wr = __ldg(&w2v[j]);
            a0 += h * wr.x; a1 += h * wr.y; a2 += h * wr.z; a3 += h * wr.w;
        }
        #pragma unroll
        for (int o = 16; o > 0; o >>= 1) {
            a0 += __shfl_xor_sync(0xffffffffu, a0, o);
            a1 += __shfl_xor_sync(0xffffffffu, a1, o);
            a2 += __shfl_xor_sync(0xffffffffu, a2, o);
            a3 += __shfl_xor_sync(0xffffffffu, a3, o);
        }
        if (lane == 0) {
            const float4 bb = __ldg(reinterpret_cast<const float4*>(b2));
            float4 ov;
            ov.x = S_SCALE_C * tanh_fast(a0 + bb.x);
            ov.y = S_SCALE_C * tanh_fast(a1 + bb.y);
            ov.z = S_SCALE_C * tanh_fast(a2 + bb.z);
            ov.w = S_SCALE_C * tanh_fast(a3 + bb.w);
            reinterpret_cast<float4*>(g_off)[blk * RB + wid] = ov;
        }
    }
    __threadfence();
    __syncthreads();

    // arrive
    if (tid == 0) {
        const unsigned t = atomicAdd(&g_cnt, 1u);
        sh_tgt = t - (t % NBLK) + NBLK;
    }

    // ============ phase B prologue (independent of g_off) ============
    float spx[2], spy[2];
    int lvl[2], bI[2], sI[2], idxI[2];
    bool valid[2];
    #pragma unroll
    for (int p = 0; p < 2; p++) {
        const int idx = blk * PER_BLK + p * NTHR + tid;
        valid[p] = (p == 0) || (tid < PER_BLK - NTHR);
        idxI[p] = idx;
        if (valid[p]) {
            const int s  = idx & 15;
            const int qb = idx >> 4;
            const int q  = qb % QQ;
            const int b  = qb / QQ;
            poly_xy(rp + ((size_t)b * QQ + q) * 8, s, spx[p], spy[p]);
            lvl[p] = rl[b * QQ + q];
            bI[p] = b; sI[p] = s;
        }
    }

    // ============ global barrier ============
    __syncthreads();
    if (tid == 0) {
        const unsigned tgt = sh_tgt;
        while ((int)(ld_cg_u32(&g_cnt) - tgt) < 0)
            __nanosleep(32);
    }
    __syncthreads();
    __threadfence();                         // acquire

    // ============ epilogue ============
    #pragma unroll
    for (int p = 0; p < 2; p++) {
        if (!valid[p]) continue;
        const float* o = g_off + (((size_t)bI[p] * QP + lvl[p]) * SNUM + sI[p]) * 4;
        const float4 ov = __ldcg(reinterpret_cast<const float4*>(o));
        float4 v;
        v.x = ov.x + spx[p];
        v.y = ov.y + spy[p];
        v.z = ov.z + spx[p];
        v.w = ov.w + spy[p];
        reinterpret_cast<float4*>(out)[idxI[p]] = v;
    }
}

extern "C" void kernel_launch(void* const* d_in, const int* in_sizes, int n_in,
                              void* d_out, int out_size) {
    const float* ref_polys = (const float*)d_in[0];
    const float* memory    = (const float*)d_in[1];
    const float* w1        = (const float*)d_in[2];
    const float* b1        = (const float*)d_in[3];
    const float* w2        = (const float*)d_in[4];
    const float* b2        = (const float*)d_in[5];
    const int*   ref_lvls  = (const int*)d_in[6];
    float* out = (float*)d_out;

    cudaFuncSetAttribute(fused_kernel,
                         cudaFuncAttributeMaxDynamicSharedMemorySize, SMEM_BYTES);
    fused_kernel<<<NBLK, NTHR, SMEM_BYTES>>>(ref_polys, memory, w1, b1, w2, b2,
                                             ref_lvls, out);
}